// round 1
// baseline (speedup 1.0000x reference)
#include <cuda_runtime.h>
#include <math.h>

#define NN 50000
#define MM 4000
#define EE 320000

// -------- scratch arenas (static __device__; no allocation allowed) --------
__device__ float g_farena[49000000];
__device__ int   g_iarena[1000000];

// ---------------------------------------------------------------------------
__global__ void k_zero_f(float* p, int n) {
    int i = blockIdx.x * blockDim.x + threadIdx.x;
    if (i < n) p[i] = 0.f;
}
__global__ void k_zero_i(int* p, int n) {
    int i = blockIdx.x * blockDim.x + threadIdx.x;
    if (i < n) p[i] = 0;
}

__global__ void k_count(const int* __restrict__ he_n, const int* __restrict__ he_e,
                        const float* __restrict__ he_w,
                        int* ncnt, int* ecnt, float* Dn) {
    int e = blockIdx.x * blockDim.x + threadIdx.x;
    if (e >= EE) return;
    int n = he_n[e], m = he_e[e];
    atomicAdd(&ncnt[n], 1);
    atomicAdd(&ecnt[m], 1);
    atomicAdd(&Dn[n], he_w[m]);
}

// single-block exclusive scan (n <= 1024*chunk)
__global__ void k_scan(const int* __restrict__ cnt, int* __restrict__ off, int n) {
    __shared__ int sh[1024];
    int t = threadIdx.x;
    int chunk = (n + 1023) >> 10;
    int base = t * chunk;
    int s = 0;
    for (int i = 0; i < chunk; i++) { int idx = base + i; if (idx < n) s += cnt[idx]; }
    sh[t] = s;
    __syncthreads();
    for (int o = 1; o < 1024; o <<= 1) {
        int v = (t >= o) ? sh[t - o] : 0;
        __syncthreads();
        sh[t] += v;
        __syncthreads();
    }
    int run = sh[t] - s;   // exclusive prefix
    for (int i = 0; i < chunk; i++) {
        int idx = base + i;
        if (idx < n) { off[idx] = run; run += cnt[idx]; }
    }
    if (t == 1023) off[n] = sh[1023];
}

__global__ void k_fill(const int* __restrict__ he_n, const int* __restrict__ he_e,
                       const int* __restrict__ noff, const int* __restrict__ eoff,
                       int* nfill, int* efill, int* nent, int* eent) {
    int e = blockIdx.x * blockDim.x + threadIdx.x;
    if (e >= EE) return;
    int n = he_n[e], m = he_e[e];
    int p = atomicAdd(&nfill[n], 1);
    nent[noff[n] + p] = e;
    int q = atomicAdd(&efill[m], 1);
    eent[eoff[m] + q] = e;
}

// precompute W @ att vectors: wx1/we1 [128][2], wx2/we2 [128]
__global__ void k_prepatt(const float* __restrict__ h1_w, const float* __restrict__ h1_att,
                          const float* __restrict__ h2_w, const float* __restrict__ h2_att,
                          float* wx1, float* we1, float* wx2, float* we2) {
    int k = threadIdx.x;
    if (k >= 128) return;
    for (int h = 0; h < 2; h++) {
        float sx = 0.f, se = 0.f;
        for (int c = 0; c < 128; c++) {
            float w = h1_w[k * 256 + h * 128 + c];
            sx += w * h1_att[h * 256 + c];
            se += w * h1_att[h * 256 + 128 + c];
        }
        wx1[k * 2 + h] = sx;
        we1[k * 2 + h] = se;
    }
    float sx = 0.f, se = 0.f;
    for (int c = 0; c < 128; c++) {
        float w = h2_w[k * 128 + c];
        sx += w * h2_att[c];
        se += w * h2_att[128 + c];
    }
    wx2[k] = sx;
    we2[k] = se;
}

// ---------------- fused GEMM: C = f(affine(A) @ W [+bias]) [+src] ----------
// A: [rows,128] row-major, W: [128,ldw], C: [rows,ldw]
template <bool AFF, bool BIAS, bool RELU, bool ADDSRC>
__global__ void __launch_bounds__(256) k_gemm(
    const float* __restrict__ A, const float* __restrict__ aff,
    const float* __restrict__ W, int ldw,
    const float* __restrict__ bias, const float* __restrict__ src,
    float* __restrict__ C, int rows) {
    int tid = threadIdx.x;
    int tx = tid & 31, ty = tid >> 5;
    int r0 = blockIdx.x * 64;
    int co0 = blockIdx.y * 128;
    const float* Wp = W + co0 + tx * 4;

    float acc[8][4];
#pragma unroll
    for (int i = 0; i < 8; i++)
#pragma unroll
        for (int j = 0; j < 4; j++) acc[i][j] = 0.f;

    const float* Ap[8];
#pragma unroll
    for (int i = 0; i < 8; i++) {
        int r = r0 + i * 8 + ty;
        if (r >= rows) r = rows - 1;
        Ap[i] = A + (size_t)r * 128;
    }

    for (int k = 0; k < 128; k += 4) {
        float4 av[8];
#pragma unroll
        for (int i = 0; i < 8; i++) av[i] = *(const float4*)(Ap[i] + k);
        if (AFF) {
            float4 s = *(const float4*)(aff + k);
            float4 t = *(const float4*)(aff + 128 + k);
#pragma unroll
            for (int i = 0; i < 8; i++) {
                av[i].x = fmaf(av[i].x, s.x, t.x);
                av[i].y = fmaf(av[i].y, s.y, t.y);
                av[i].z = fmaf(av[i].z, s.z, t.z);
                av[i].w = fmaf(av[i].w, s.w, t.w);
            }
        }
#pragma unroll
        for (int kk = 0; kk < 4; kk++) {
            float4 b = *(const float4*)(Wp + (size_t)(k + kk) * ldw);
#pragma unroll
            for (int i = 0; i < 8; i++) {
                float a = (kk == 0) ? av[i].x : (kk == 1) ? av[i].y : (kk == 2) ? av[i].z : av[i].w;
                acc[i][0] = fmaf(a, b.x, acc[i][0]);
                acc[i][1] = fmaf(a, b.y, acc[i][1]);
                acc[i][2] = fmaf(a, b.z, acc[i][2]);
                acc[i][3] = fmaf(a, b.w, acc[i][3]);
            }
        }
    }
#pragma unroll
    for (int i = 0; i < 8; i++) {
        int r = r0 + i * 8 + ty;
        if (r < rows) {
#pragma unroll
            for (int j = 0; j < 4; j++) {
                int cg = co0 + tx * 4 + j;
                float v = acc[i][j];
                if (BIAS) v += bias[cg];
                if (RELU) v = (v >= 0.f) ? v : 0.2f * v;
                if (ADDSRC) v += src[(size_t)r * ldw + cg];
                C[(size_t)r * ldw + cg] = v;
            }
        }
    }
}

// column sums + sums of squares (for BN) -> st[0..127]=sum, st[128..255]=sumsq
__global__ void k_colstats(const float* __restrict__ X, int rows, float* __restrict__ st) {
    int c = threadIdx.x;
    int r0 = blockIdx.x * 256;
    int r1 = min(r0 + 256, rows);
    float s = 0.f, q = 0.f;
    for (int r = r0; r < r1; r++) {
        float v = X[(size_t)r * 128 + c];
        s += v;
        q += v * v;
    }
    atomicAdd(&st[c], s);
    atomicAdd(&st[128 + c], q);
}

__global__ void k_affine(const float* __restrict__ st, const float* __restrict__ g,
                         const float* __restrict__ b, float* __restrict__ aff, float invn) {
    int c = threadIdx.x;
    float m = st[c] * invn;
    float var = st[128 + c] * invn - m * m;
    float sc = g[c] * rsqrtf(var + 1e-5f);
    aff[c] = sc;
    aff[128 + c] = b[c] - sc * m;
}

// out[row,h] = affine(X[row,:]) . V[:,h]
template <int H, bool AFF>
__global__ void k_rowvec(const float* __restrict__ X, const float* __restrict__ aff,
                         const float* __restrict__ V, float* __restrict__ out, int rows) {
    int row = blockIdx.x * 8 + (threadIdx.x >> 5);
    if (row >= rows) return;
    int lane = threadIdx.x & 31;
    float p[H];
#pragma unroll
    for (int h = 0; h < H; h++) p[h] = 0.f;
    for (int k = lane; k < 128; k += 32) {
        float v = X[(size_t)row * 128 + k];
        if (AFF) v = fmaf(v, aff[k], aff[128 + k]);
#pragma unroll
        for (int h = 0; h < H; h++) p[h] += v * V[k * H + h];
    }
#pragma unroll
    for (int h = 0; h < H; h++) {
        for (int o = 16; o; o >>= 1) p[h] += __shfl_xor_sync(0xffffffffu, p[h], o);
        if (lane == 0) out[(size_t)row * H + h] = p[h];
    }
}

// ea[m,:] = sum over entries of edge m of affine(Z[he_n[e],:])
__global__ void k_ea(const float* __restrict__ Z, const float* __restrict__ aff,
                     const int* __restrict__ eoff, const int* __restrict__ entries,
                     const int* __restrict__ he_n, float* __restrict__ ea) {
    int m = blockIdx.x;
    int tid = threadIdx.x;
    int off = eoff[m];
    int cnt = eoff[m + 1] - off;
    float sc = aff[tid], sh = aff[128 + tid];
    __shared__ int sn[128];
    float s = 0.f;
    for (int base = 0; base < cnt; base += 128) {
        int nb = min(128, cnt - base);
        __syncthreads();
        if (tid < nb) {
            int e = entries[off + base + tid];
            sn[tid] = he_n[e];
        }
        __syncthreads();
        for (int j = 0; j < nb; j++) s += fmaf(Z[(size_t)sn[j] * 128 + tid], sc, sh);
    }
    ea[(size_t)m * 128 + tid] = s;
}

// per-node segment softmax over lrelu(a_node + a_edge)
template <int H>
__global__ void k_softmax(const float* __restrict__ anode, const float* __restrict__ aedge,
                          const int* __restrict__ noff, const int* __restrict__ entries,
                          const int* __restrict__ he_e, float* __restrict__ a, int rows) {
    int n = blockIdx.x * 8 + (threadIdx.x >> 5);
    if (n >= rows) return;
    int lane = threadIdx.x & 31;
    int off = noff[n];
    int deg = noff[n + 1] - off;
    if (deg == 0) return;
#pragma unroll
    for (int h = 0; h < H; h++) {
        float an = anode[(size_t)n * H + h];
        float mx = -1e30f;
        for (int i = lane; i < deg; i += 32) {
            int e = entries[off + i];
            int m = he_e[e];
            float l = an + aedge[(size_t)m * H + h];
            l = (l >= 0.f) ? l : 0.2f * l;
            a[(size_t)e * H + h] = l;
            mx = fmaxf(mx, l);
        }
        for (int o = 16; o; o >>= 1) mx = fmaxf(mx, __shfl_xor_sync(0xffffffffu, mx, o));
        float s = 0.f;
        for (int i = lane; i < deg; i += 32) {
            int e = entries[off + i];
            float v = expf(a[(size_t)e * H + h] - mx);
            a[(size_t)e * H + h] = v;
            s += v;
        }
        for (int o = 16; o; o >>= 1) s += __shfl_xor_sync(0xffffffffu, s, o);
        float inv = 1.f / s;
        for (int i = lane; i < deg; i += 32) {
            int e = entries[off + i];
            a[(size_t)e * H + h] *= inv;
        }
    }
}

// eo[m,h,:] = Binv * sum_e a[e,h] * XL[he_n[e],h,:]
template <int H>
__global__ void k_eo(const float* __restrict__ XL, const float* __restrict__ a,
                     const int* __restrict__ eoff, const int* __restrict__ entries,
                     const int* __restrict__ he_n, float* __restrict__ eo) {
    int m = blockIdx.x;
    int tid = threadIdx.x;
    int h = tid >> 7;
    int c = tid & 127;
    int off = eoff[m];
    int cnt = eoff[m + 1] - off;
    __shared__ int sn[64];
    __shared__ float sw[64 * H];
    float acc = 0.f;
    for (int base = 0; base < cnt; base += 64) {
        int nb = min(64, cnt - base);
        __syncthreads();
        if (tid < nb) {
            int e = entries[off + base + tid];
            sn[tid] = he_n[e];
#pragma unroll
            for (int hh = 0; hh < H; hh++) sw[tid * H + hh] = a[(size_t)e * H + hh];
        }
        __syncthreads();
        for (int j = 0; j < nb; j++)
            acc = fmaf(sw[j * H + h], XL[(size_t)sn[j] * (128 * H) + h * 128 + c], acc);
    }
    float binv = cnt ? 1.f / (float)cnt : 0.f;
    eo[(size_t)m * (128 * H) + h * 128 + c] = acc * binv;
}

// U[n,:] = affine(Z[n,:]) + Dinv * mean_h sum_e a[e,h]*eo[he_e[e],h,:] + hb
template <int H>
__global__ void k_out(const float* __restrict__ eo, const float* __restrict__ a,
                      const int* __restrict__ noff, const int* __restrict__ entries,
                      const int* __restrict__ he_e, const float* __restrict__ Z,
                      const float* __restrict__ aff, const float* __restrict__ hb,
                      const float* __restrict__ Dn, float* __restrict__ U, int rows) {
    int n = blockIdx.x * 8 + (threadIdx.x >> 5);
    if (n >= rows) return;
    int lane = threadIdx.x & 31;
    int off = noff[n];
    int deg = noff[n + 1] - off;
    float acc[H][4];
#pragma unroll
    for (int h = 0; h < H; h++)
#pragma unroll
        for (int j = 0; j < 4; j++) acc[h][j] = 0.f;
    for (int i = 0; i < deg; i++) {
        int e = entries[off + i];
        int m = he_e[e];
#pragma unroll
        for (int h = 0; h < H; h++) {
            float w = a[(size_t)e * H + h];
#pragma unroll
            for (int j = 0; j < 4; j++)
                acc[h][j] = fmaf(w, eo[(size_t)m * (128 * H) + h * 128 + lane + 32 * j], acc[h][j]);
        }
    }
    float dn = Dn[n];
    float dinv = (dn > 0.f) ? 1.f / dn : 0.f;
#pragma unroll
    for (int j = 0; j < 4; j++) {
        int c = lane + 32 * j;
        float xb = fmaf(Z[(size_t)n * 128 + c], aff[c], aff[128 + c]);
        float o = (H == 2) ? 0.5f * (acc[0][j] + acc[1][j]) : acc[0][j];
        U[(size_t)n * 128 + c] = xb + dinv * o + hb[c];
    }
}

__global__ void k_final(const float* __restrict__ wb, const float* __restrict__ aff,
                        float* __restrict__ out, int total) {
    int i = blockIdx.x * blockDim.x + threadIdx.x;
    if (i < total) {
        int c = i & 127;
        out[i] = fmaf(wb[i], aff[c], aff[128 + c]);
    }
}

// ---------------------------------------------------------------------------
extern "C" void kernel_launch(void* const* d_in, const int* in_sizes, int n_in,
                              void* d_out, int out_size) {
    const float* x      = (const float*)d_in[0];
    const int*   he_n   = (const int*)d_in[1];
    const int*   he_e   = (const int*)d_in[2];
    const float* he_w   = (const float*)d_in[3];
    const float* lin1_w = (const float*)d_in[4];
    const float* lin1_b = (const float*)d_in[5];
    const float* bn1_g  = (const float*)d_in[6];
    const float* bn1_b  = (const float*)d_in[7];
    const float* h1_w   = (const float*)d_in[8];
    const float* h1_att = (const float*)d_in[9];
    const float* h1_b   = (const float*)d_in[10];
    const float* bn2_g  = (const float*)d_in[11];
    const float* bn2_b  = (const float*)d_in[12];
    const float* h2_w   = (const float*)d_in[13];
    const float* h2_att = (const float*)d_in[14];
    const float* h2_b   = (const float*)d_in[15];
    const float* bn3_g  = (const float*)d_in[16];
    const float* bn3_b  = (const float*)d_in[17];
    const float* lin2_w = (const float*)d_in[18];
    const float* lin2_b = (const float*)d_in[19];
    const float* bn4_g  = (const float*)d_in[20];
    const float* bn4_b  = (const float*)d_in[21];
    float* out = (float*)d_out;

    float* F = nullptr;
    int*   I = nullptr;
    cudaGetSymbolAddress((void**)&F, g_farena);
    cudaGetSymbolAddress((void**)&I, g_iarena);

    // float arena layout
    float* p_Dn   = F;                     // 50000
    float* p_st   = p_Dn + 50000;          // 1024 (4 BNs x 256)
    float* p_aff  = p_st + 1024;           // 1024 (4 BNs x 256)
    float* p_wx1  = p_aff + 1024;          // 256
    float* p_we1  = p_wx1 + 256;           // 256
    float* p_wx2  = p_we1 + 256;           // 128
    float* p_we2  = p_wx2 + 128;           // 128
    float* p_z1   = p_we2 + 128;           // 6.4M
    float* p_xl1  = p_z1 + 6400000;        // 12.8M
    float* p_u1   = p_xl1 + 12800000;      // 6.4M
    float* p_xl2  = p_u1 + 6400000;        // 6.4M
    float* p_u2   = p_xl2 + 6400000;       // 6.4M
    float* p_wbuf = p_u2 + 6400000;        // 6.4M
    float* p_ea   = p_wbuf + 6400000;      // 512000
    float* p_ea2  = p_ea + 512000;         // 512000
    float* p_eo1  = p_ea2 + 512000;        // 1024000
    float* p_eo2  = p_eo1 + 1024000;       // 512000
    float* p_a1   = p_eo2 + 512000;        // 640000
    float* p_a2   = p_a1 + 640000;         // 320000
    float* p_an1  = p_a2 + 320000;         // 100000
    float* p_ae1  = p_an1 + 100000;        // 8000
    float* p_an2  = p_ae1 + 8000;          // 50000
    float* p_ae2  = p_an2 + 50000;         // 4000

    // int arena layout
    int* p_ncnt  = I;                      // 50000
    int* p_nfill = p_ncnt + 50000;         // 50000
    int* p_ecnt  = p_nfill + 50000;        // 4000
    int* p_efill = p_ecnt + 4000;          // 4000   (first 108000 ints zeroed)
    int* p_noff  = p_efill + 4000;         // 50001
    int* p_eoff  = p_noff + 50001;         // 4001
    int* p_nent  = p_eoff + 4001;          // 320000
    int* p_eent  = p_nent + 320000;        // 320000

    const float invn = 1.f / (float)NN;
    const int EB = (EE + 255) / 256;       // 1250
    const int NWB = (NN + 7) / 8;          // 6250 (warp-per-node kernels)
    const int MWB = (MM + 7) / 8;          // 500
    const int GB = (NN + 63) / 64;         // 782
    const int SB = (NN + 255) / 256;       // 196

    // ---- zero counters / stats ----
    k_zero_i<<<(108000 + 255) / 256, 256>>>(I, 108000);
    k_zero_f<<<(51024 + 255) / 256, 256>>>(F, 51024);   // Dn + stats

    // ---- CSR build ----
    k_count<<<EB, 256>>>(he_n, he_e, he_w, p_ncnt, p_ecnt, p_Dn);
    k_scan<<<1, 1024>>>(p_ncnt, p_noff, NN);
    k_scan<<<1, 1024>>>(p_ecnt, p_eoff, MM);
    k_fill<<<EB, 256>>>(he_n, he_e, p_noff, p_eoff, p_nfill, p_efill, p_nent, p_eent);
    k_prepatt<<<1, 128>>>(h1_w, h1_att, h2_w, h2_att, p_wx1, p_we1, p_wx2, p_we2);

    // ---- layer 1: z1 = lrelu(x @ lin1_w + b); BN1 -> aff1 ----
    k_gemm<false, true, true, false><<<dim3(GB, 1), 256>>>(x, nullptr, lin1_w, 128, lin1_b, nullptr, p_z1, NN);
    k_colstats<<<SB, 128>>>(p_z1, NN, p_st);
    k_affine<<<1, 128>>>(p_st, bn1_g, bn1_b, p_aff, invn);

    // ---- hgconv1 (H=2) ----
    k_gemm<true, false, false, false><<<dim3(GB, 2), 256>>>(p_z1, p_aff, h1_w, 256, nullptr, nullptr, p_xl1, NN);
    k_rowvec<2, true><<<NWB, 256>>>(p_z1, p_aff, p_wx1, p_an1, NN);
    k_ea<<<MM, 128>>>(p_z1, p_aff, p_eoff, p_eent, he_n, p_ea);
    k_rowvec<2, false><<<MWB, 256>>>(p_ea, nullptr, p_we1, p_ae1, MM);
    k_softmax<2><<<NWB, 256>>>(p_an1, p_ae1, p_noff, p_nent, he_e, p_a1, NN);
    k_eo<2><<<MM, 256>>>(p_xl1, p_a1, p_eoff, p_eent, he_n, p_eo1);
    k_out<2><<<NWB, 256>>>(p_eo1, p_a1, p_noff, p_nent, he_e, p_z1, p_aff, h1_b, p_Dn, p_u1, NN);
    k_colstats<<<SB, 128>>>(p_u1, NN, p_st + 256);
    k_affine<<<1, 128>>>(p_st + 256, bn2_g, bn2_b, p_aff + 256, invn);

    // ---- hgconv2 (H=1) ----
    k_gemm<true, false, false, false><<<dim3(GB, 1), 256>>>(p_u1, p_aff + 256, h2_w, 128, nullptr, nullptr, p_xl2, NN);
    k_rowvec<1, true><<<NWB, 256>>>(p_u1, p_aff + 256, p_wx2, p_an2, NN);
    k_ea<<<MM, 128>>>(p_u1, p_aff + 256, p_eoff, p_eent, he_n, p_ea2);
    k_rowvec<1, false><<<MWB, 256>>>(p_ea2, nullptr, p_we2, p_ae2, MM);
    k_softmax<1><<<NWB, 256>>>(p_an2, p_ae2, p_noff, p_nent, he_e, p_a2, NN);
    k_eo<1><<<MM, 128>>>(p_xl2, p_a2, p_eoff, p_eent, he_n, p_eo2);
    k_out<1><<<NWB, 256>>>(p_eo2, p_a2, p_noff, p_nent, he_e, p_u1, p_aff + 256, h2_b, p_Dn, p_u2, NN);
    k_colstats<<<SB, 128>>>(p_u2, NN, p_st + 512);
    k_affine<<<1, 128>>>(p_st + 512, bn3_g, bn3_b, p_aff + 512, invn);

    // ---- final: w = x + lrelu(affine3(u2) @ lin2_w + b2); BN4; out ----
    k_gemm<true, true, true, true><<<dim3(GB, 1), 256>>>(p_u2, p_aff + 512, lin2_w, 128, lin2_b, x, p_wbuf, NN);
    k_colstats<<<SB, 128>>>(p_wbuf, NN, p_st + 768);
    k_affine<<<1, 128>>>(p_st + 768, bn4_g, bn4_b, p_aff + 768, invn);
    k_final<<<(NN * 128 + 255) / 256, 256>>>(p_wbuf, p_aff + 768, out, NN * 128);
}

// round 2
// speedup vs baseline: 1.0980x; 1.0980x over previous
#include <cuda_runtime.h>
#include <math.h>

#define NN 50000
#define MM 4000
#define EE 320000

// -------- scratch arenas (static __device__; no allocation allowed) --------
__device__ float g_farena[49000000];
__device__ int   g_iarena[1000000];

// ---------------------------------------------------------------------------
__global__ void k_zero_f(float* p, int n) {
    int i = blockIdx.x * blockDim.x + threadIdx.x;
    if (i < n) p[i] = 0.f;
}
__global__ void k_zero_i(int* p, int n) {
    int i = blockIdx.x * blockDim.x + threadIdx.x;
    if (i < n) p[i] = 0;
}

__global__ void k_count(const int* __restrict__ he_n, const int* __restrict__ he_e,
                        const float* __restrict__ he_w,
                        int* ncnt, int* ecnt, float* Dn) {
    int e = blockIdx.x * blockDim.x + threadIdx.x;
    if (e >= EE) return;
    int n = he_n[e], m = he_e[e];
    atomicAdd(&ncnt[n], 1);
    atomicAdd(&ecnt[m], 1);
    atomicAdd(&Dn[n], he_w[m]);
}

// ---- parallel 3-phase exclusive scan --------------------------------------
__global__ void k_scan_red(const int* __restrict__ cnt, int* __restrict__ bsum, int n) {
    __shared__ int sh[256];
    int t = threadIdx.x;
    int i = blockIdx.x * 256 + t;
    sh[t] = (i < n) ? cnt[i] : 0;
    __syncthreads();
    for (int o = 128; o; o >>= 1) {
        if (t < o) sh[t] += sh[t + o];
        __syncthreads();
    }
    if (t == 0) bsum[blockIdx.x] = sh[0];
}
// single block: exclusive scan of nb (<=256) block sums; also writes off[n]=total
__global__ void k_scan_top(const int* __restrict__ bsum, int* __restrict__ boff,
                           int nb, int* __restrict__ off, int n) {
    __shared__ int sh[256];
    int t = threadIdx.x;
    int v = (t < nb) ? bsum[t] : 0;
    sh[t] = v;
    __syncthreads();
    for (int o = 1; o < 256; o <<= 1) {
        int u = (t >= o) ? sh[t - o] : 0;
        __syncthreads();
        sh[t] += u;
        __syncthreads();
    }
    if (t < nb) boff[t] = sh[t] - v;
    if (t == 255) off[n] = sh[255];
}
__global__ void k_scan_fin(const int* __restrict__ cnt, const int* __restrict__ boff,
                           int* __restrict__ off, int n) {
    __shared__ int sh[256];
    int t = threadIdx.x;
    int i = blockIdx.x * 256 + t;
    int v = (i < n) ? cnt[i] : 0;
    sh[t] = v;
    __syncthreads();
    for (int o = 1; o < 256; o <<= 1) {
        int u = (t >= o) ? sh[t - o] : 0;
        __syncthreads();
        sh[t] += u;
        __syncthreads();
    }
    if (i < n) off[i] = boff[blockIdx.x] + sh[t] - v;
}

__global__ void k_fill(const int* __restrict__ he_n, const int* __restrict__ he_e,
                       const int* __restrict__ noff, const int* __restrict__ eoff,
                       int* nfill, int* efill, int* nent, int* eent) {
    int e = blockIdx.x * blockDim.x + threadIdx.x;
    if (e >= EE) return;
    int n = he_n[e], m = he_e[e];
    int p = atomicAdd(&nfill[n], 1);
    nent[noff[n] + p] = e;
    int q = atomicAdd(&efill[m], 1);
    eent[eoff[m] + q] = e;
}

// precompute W @ att vectors: wx1/we1 [128][2], wx2/we2 [128]
__global__ void k_prepatt(const float* __restrict__ h1_w, const float* __restrict__ h1_att,
                          const float* __restrict__ h2_w, const float* __restrict__ h2_att,
                          float* wx1, float* we1, float* wx2, float* we2) {
    int k = threadIdx.x;
    if (k >= 128) return;
    for (int h = 0; h < 2; h++) {
        float sx = 0.f, se = 0.f;
        for (int c = 0; c < 128; c++) {
            float w = h1_w[k * 256 + h * 128 + c];
            sx += w * h1_att[h * 256 + c];
            se += w * h1_att[h * 256 + 128 + c];
        }
        wx1[k * 2 + h] = sx;
        we1[k * 2 + h] = se;
    }
    float sx = 0.f, se = 0.f;
    for (int c = 0; c < 128; c++) {
        float w = h2_w[k * 128 + c];
        sx += w * h2_att[c];
        se += w * h2_att[128 + c];
    }
    wx2[k] = sx;
    we2[k] = se;
}

// -------------------- packed f32x2 helpers ---------------------------------
__device__ __forceinline__ void ffma2(unsigned long long& d, unsigned long long a,
                                      unsigned long long b) {
    asm("fma.rn.f32x2 %0, %1, %2, %0;" : "+l"(d) : "l"(a), "l"(b));
}
__device__ __forceinline__ unsigned long long pack2(float x) {
    unsigned long long r;
    asm("mov.b64 %0, {%1, %1};" : "=l"(r) : "f"(x));
    return r;
}
__device__ __forceinline__ float lo32(unsigned long long v) {
    return __uint_as_float((unsigned)v);
}
__device__ __forceinline__ float hi32(unsigned long long v) {
    return __uint_as_float((unsigned)(v >> 32));
}

// ---------------- fused GEMM: C = f(affine(A) @ W [+bias]) [+src] ----------
// A: [rows,128] row-major, W: [128,ldw], C: [rows,ldw]
// tile 128x128 per 256-thread block, 8x8 per thread, f32x2 accumulators.
// STATS: accumulate per-column sum/sumsq of the STORED value into st[0..127]/st[128..255]
template <bool AFF, bool BIAS, bool RELU, bool ADDSRC, bool STATS>
__global__ void __launch_bounds__(256) k_gemm2(
    const float* __restrict__ A, const float* __restrict__ aff,
    const float* __restrict__ W, int ldw,
    const float* __restrict__ bias, const float* __restrict__ src,
    float* __restrict__ C, int rows, float* __restrict__ st) {
    __shared__ float ssum[256];
    int tid = threadIdx.x;
    int cg = tid & 15, rg = tid >> 4;
    int col0 = blockIdx.y * 128 + cg * 8;
    int row0 = blockIdx.x * 128 + rg * 8;

    if (STATS) {
        ssum[tid] = 0.f;
        __syncthreads();
    }

    unsigned long long acc[8][4];
#pragma unroll
    for (int i = 0; i < 8; i++)
#pragma unroll
        for (int j = 0; j < 4; j++) acc[i][j] = 0ull;

    const float* Ap[8];
#pragma unroll
    for (int i = 0; i < 8; i++) {
        int r = row0 + i;
        if (r >= rows) r = rows - 1;
        Ap[i] = A + (size_t)r * 128;
    }
    const float* Wp = W + col0;

#pragma unroll 2
    for (int k = 0; k < 128; k += 4) {
        float4 av[8];
#pragma unroll
        for (int i = 0; i < 8; i++) av[i] = *(const float4*)(Ap[i] + k);
        if (AFF) {
            float4 s = *(const float4*)(aff + k);
            float4 t = *(const float4*)(aff + 128 + k);
#pragma unroll
            for (int i = 0; i < 8; i++) {
                av[i].x = fmaf(av[i].x, s.x, t.x);
                av[i].y = fmaf(av[i].y, s.y, t.y);
                av[i].z = fmaf(av[i].z, s.z, t.z);
                av[i].w = fmaf(av[i].w, s.w, t.w);
            }
        }
#pragma unroll
        for (int kk = 0; kk < 4; kk++) {
            const ulonglong2* wrow = (const ulonglong2*)(Wp + (size_t)(k + kk) * ldw);
            ulonglong2 b01 = wrow[0];
            ulonglong2 b23 = wrow[1];
#pragma unroll
            for (int i = 0; i < 8; i++) {
                float a = (kk == 0) ? av[i].x : (kk == 1) ? av[i].y
                          : (kk == 2) ? av[i].z : av[i].w;
                unsigned long long aa = pack2(a);
                ffma2(acc[i][0], aa, b01.x);
                ffma2(acc[i][1], aa, b01.y);
                ffma2(acc[i][2], aa, b23.x);
                ffma2(acc[i][3], aa, b23.y);
            }
        }
    }

    float csum[8], csq[8];
    if (STATS) {
#pragma unroll
        for (int j = 0; j < 8; j++) csum[j] = csq[j] = 0.f;
    }

#pragma unroll
    for (int i = 0; i < 8; i++) {
        int r = row0 + i;
        bool valid = (r < rows);
        float v[8];
#pragma unroll
        for (int j = 0; j < 4; j++) {
            v[2 * j]     = lo32(acc[i][j]);
            v[2 * j + 1] = hi32(acc[i][j]);
        }
#pragma unroll
        for (int j = 0; j < 8; j++) {
            if (BIAS) v[j] += bias[col0 + j];
            if (RELU) v[j] = (v[j] >= 0.f) ? v[j] : 0.2f * v[j];
        }
        if (ADDSRC && valid) {
            float4 s0 = *(const float4*)(src + (size_t)r * ldw + col0);
            float4 s1 = *(const float4*)(src + (size_t)r * ldw + col0 + 4);
            v[0] += s0.x; v[1] += s0.y; v[2] += s0.z; v[3] += s0.w;
            v[4] += s1.x; v[5] += s1.y; v[6] += s1.z; v[7] += s1.w;
        }
        if (valid) {
            *(float4*)(C + (size_t)r * ldw + col0)     = make_float4(v[0], v[1], v[2], v[3]);
            *(float4*)(C + (size_t)r * ldw + col0 + 4) = make_float4(v[4], v[5], v[6], v[7]);
            if (STATS) {
#pragma unroll
                for (int j = 0; j < 8; j++) {
                    csum[j] += v[j];
                    csq[j] = fmaf(v[j], v[j], csq[j]);
                }
            }
        }
    }

    if (STATS) {
#pragma unroll
        for (int j = 0; j < 8; j++) {
            atomicAdd(&ssum[cg * 8 + j], csum[j]);
            atomicAdd(&ssum[128 + cg * 8 + j], csq[j]);
        }
        __syncthreads();
        if (tid < 128) {
            atomicAdd(&st[tid], ssum[tid]);
            atomicAdd(&st[128 + tid], ssum[128 + tid]);
        }
    }
}

// column sums + sums of squares (for BN) -> st[0..127]=sum, st[128..255]=sumsq
__global__ void k_colstats(const float* __restrict__ X, int rows, float* __restrict__ st) {
    int c = threadIdx.x;
    int r0 = blockIdx.x * 256;
    int r1 = min(r0 + 256, rows);
    float s = 0.f, q = 0.f;
    for (int r = r0; r < r1; r++) {
        float v = X[(size_t)r * 128 + c];
        s += v;
        q = fmaf(v, v, q);
    }
    atomicAdd(&st[c], s);
    atomicAdd(&st[128 + c], q);
}

__global__ void k_affine(const float* __restrict__ st, const float* __restrict__ g,
                         const float* __restrict__ b, float* __restrict__ aff, float invn) {
    int c = threadIdx.x;
    float m = st[c] * invn;
    float var = st[128 + c] * invn - m * m;
    float sc = g[c] * rsqrtf(var + 1e-5f);
    aff[c] = sc;
    aff[128 + c] = b[c] - sc * m;
}

// out[row,h] = affine(X[row,:]) . V[:,h]
template <int H, bool AFF>
__global__ void k_rowvec(const float* __restrict__ X, const float* __restrict__ aff,
                         const float* __restrict__ V, float* __restrict__ out, int rows) {
    int row = blockIdx.x * 8 + (threadIdx.x >> 5);
    if (row >= rows) return;
    int lane = threadIdx.x & 31;
    float p[H];
#pragma unroll
    for (int h = 0; h < H; h++) p[h] = 0.f;
    for (int k = lane; k < 128; k += 32) {
        float v = X[(size_t)row * 128 + k];
        if (AFF) v = fmaf(v, aff[k], aff[128 + k]);
#pragma unroll
        for (int h = 0; h < H; h++) p[h] += v * V[k * H + h];
    }
#pragma unroll
    for (int h = 0; h < H; h++) {
        for (int o = 16; o; o >>= 1) p[h] += __shfl_xor_sync(0xffffffffu, p[h], o);
        if (lane == 0) out[(size_t)row * H + h] = p[h];
    }
}

// ea[m,:] = sum over entries of edge m of affine(Z[he_n[e],:])
__global__ void k_ea(const float* __restrict__ Z, const float* __restrict__ aff,
                     const int* __restrict__ eoff, const int* __restrict__ entries,
                     const int* __restrict__ he_n, float* __restrict__ ea) {
    int m = blockIdx.x;
    int tid = threadIdx.x;
    int off = eoff[m];
    int cnt = eoff[m + 1] - off;
    float sc = aff[tid], sh = aff[128 + tid];
    __shared__ int sn[128];
    float s = 0.f;
    for (int base = 0; base < cnt; base += 128) {
        int nb = min(128, cnt - base);
        __syncthreads();
        if (tid < nb) {
            int e = entries[off + base + tid];
            sn[tid] = he_n[e];
        }
        __syncthreads();
        for (int j = 0; j < nb; j++) s += fmaf(Z[(size_t)sn[j] * 128 + tid], sc, sh);
    }
    ea[(size_t)m * 128 + tid] = s;
}

// per-node segment softmax over lrelu(a_node + a_edge)
template <int H>
__global__ void k_softmax(const float* __restrict__ anode, const float* __restrict__ aedge,
                          const int* __restrict__ noff, const int* __restrict__ entries,
                          const int* __restrict__ he_e, float* __restrict__ a, int rows) {
    int n = blockIdx.x * 8 + (threadIdx.x >> 5);
    if (n >= rows) return;
    int lane = threadIdx.x & 31;
    int off = noff[n];
    int deg = noff[n + 1] - off;
    if (deg == 0) return;
#pragma unroll
    for (int h = 0; h < H; h++) {
        float an = anode[(size_t)n * H + h];
        float mx = -1e30f;
        for (int i = lane; i < deg; i += 32) {
            int e = entries[off + i];
            int m = he_e[e];
            float l = an + aedge[(size_t)m * H + h];
            l = (l >= 0.f) ? l : 0.2f * l;
            a[(size_t)e * H + h] = l;
            mx = fmaxf(mx, l);
        }
        for (int o = 16; o; o >>= 1) mx = fmaxf(mx, __shfl_xor_sync(0xffffffffu, mx, o));
        float s = 0.f;
        for (int i = lane; i < deg; i += 32) {
            int e = entries[off + i];
            float v = expf(a[(size_t)e * H + h] - mx);
            a[(size_t)e * H + h] = v;
            s += v;
        }
        for (int o = 16; o; o >>= 1) s += __shfl_xor_sync(0xffffffffu, s, o);
        float inv = 1.f / s;
        for (int i = lane; i < deg; i += 32) {
            int e = entries[off + i];
            a[(size_t)e * H + h] *= inv;
        }
    }
}

// eo[m,h,:] = Binv * sum_e a[e,h] * XL[he_n[e],h,:]
template <int H>
__global__ void k_eo(const float* __restrict__ XL, const float* __restrict__ a,
                     const int* __restrict__ eoff, const int* __restrict__ entries,
                     const int* __restrict__ he_n, float* __restrict__ eo) {
    int m = blockIdx.x;
    int tid = threadIdx.x;
    int h = tid >> 7;
    int c = tid & 127;
    int off = eoff[m];
    int cnt = eoff[m + 1] - off;
    __shared__ int sn[64];
    __shared__ float sw[64 * H];
    float acc = 0.f;
    for (int base = 0; base < cnt; base += 64) {
        int nb = min(64, cnt - base);
        __syncthreads();
        if (tid < nb) {
            int e = entries[off + base + tid];
            sn[tid] = he_n[e];
#pragma unroll
            for (int hh = 0; hh < H; hh++) sw[tid * H + hh] = a[(size_t)e * H + hh];
        }
        __syncthreads();
        for (int j = 0; j < nb; j++)
            acc = fmaf(sw[j * H + h], XL[(size_t)sn[j] * (128 * H) + h * 128 + c], acc);
    }
    float binv = cnt ? 1.f / (float)cnt : 0.f;
    eo[(size_t)m * (128 * H) + h * 128 + c] = acc * binv;
}

// U[n,:] = affine(Z[n,:]) + Dinv * mean_h sum_e a[e,h]*eo[he_e[e],h,:] + hb
template <int H>
__global__ void k_out(const float* __restrict__ eo, const float* __restrict__ a,
                      const int* __restrict__ noff, const int* __restrict__ entries,
                      const int* __restrict__ he_e, const float* __restrict__ Z,
                      const float* __restrict__ aff, const float* __restrict__ hb,
                      const float* __restrict__ Dn, float* __restrict__ U, int rows) {
    int n = blockIdx.x * 8 + (threadIdx.x >> 5);
    if (n >= rows) return;
    int lane = threadIdx.x & 31;
    int off = noff[n];
    int deg = noff[n + 1] - off;
    float acc[H][4];
#pragma unroll
    for (int h = 0; h < H; h++)
#pragma unroll
        for (int j = 0; j < 4; j++) acc[h][j] = 0.f;
    for (int i = 0; i < deg; i++) {
        int e = entries[off + i];
        int m = he_e[e];
#pragma unroll
        for (int h = 0; h < H; h++) {
            float w = a[(size_t)e * H + h];
#pragma unroll
            for (int j = 0; j < 4; j++)
                acc[h][j] = fmaf(w, eo[(size_t)m * (128 * H) + h * 128 + lane + 32 * j], acc[h][j]);
        }
    }
    float dn = Dn[n];
    float dinv = (dn > 0.f) ? 1.f / dn : 0.f;
#pragma unroll
    for (int j = 0; j < 4; j++) {
        int c = lane + 32 * j;
        float xb = fmaf(Z[(size_t)n * 128 + c], aff[c], aff[128 + c]);
        float o = (H == 2) ? 0.5f * (acc[0][j] + acc[1][j]) : acc[0][j];
        U[(size_t)n * 128 + c] = xb + dinv * o + hb[c];
    }
}

__global__ void k_final(const float* __restrict__ wb, const float* __restrict__ aff,
                        float* __restrict__ out, int total) {
    int i = blockIdx.x * blockDim.x + threadIdx.x;
    if (i < total) {
        int c = i & 127;
        out[i] = fmaf(wb[i], aff[c], aff[128 + c]);
    }
}

// ---------------------------------------------------------------------------
extern "C" void kernel_launch(void* const* d_in, const int* in_sizes, int n_in,
                              void* d_out, int out_size) {
    const float* x      = (const float*)d_in[0];
    const int*   he_n   = (const int*)d_in[1];
    const int*   he_e   = (const int*)d_in[2];
    const float* he_w   = (const float*)d_in[3];
    const float* lin1_w = (const float*)d_in[4];
    const float* lin1_b = (const float*)d_in[5];
    const float* bn1_g  = (const float*)d_in[6];
    const float* bn1_b  = (const float*)d_in[7];
    const float* h1_w   = (const float*)d_in[8];
    const float* h1_att = (const float*)d_in[9];
    const float* h1_b   = (const float*)d_in[10];
    const float* bn2_g  = (const float*)d_in[11];
    const float* bn2_b  = (const float*)d_in[12];
    const float* h2_w   = (const float*)d_in[13];
    const float* h2_att = (const float*)d_in[14];
    const float* h2_b   = (const float*)d_in[15];
    const float* bn3_g  = (const float*)d_in[16];
    const float* bn3_b  = (const float*)d_in[17];
    const float* lin2_w = (const float*)d_in[18];
    const float* lin2_b = (const float*)d_in[19];
    const float* bn4_g  = (const float*)d_in[20];
    const float* bn4_b  = (const float*)d_in[21];
    float* out = (float*)d_out;

    float* F = nullptr;
    int*   I = nullptr;
    cudaGetSymbolAddress((void**)&F, g_farena);
    cudaGetSymbolAddress((void**)&I, g_iarena);

    // float arena layout
    float* p_Dn   = F;                     // 50000
    float* p_st   = p_Dn + 50000;          // 1024 (4 BNs x 256)
    float* p_aff  = p_st + 1024;           // 1024 (4 BNs x 256)
    float* p_wx1  = p_aff + 1024;          // 256
    float* p_we1  = p_wx1 + 256;           // 256
    float* p_wx2  = p_we1 + 256;           // 128
    float* p_we2  = p_wx2 + 128;           // 128
    float* p_z1   = p_we2 + 128;           // 6.4M
    float* p_xl1  = p_z1 + 6400000;        // 12.8M
    float* p_u1   = p_xl1 + 12800000;      // 6.4M
    float* p_xl2  = p_u1 + 6400000;        // 6.4M
    float* p_u2   = p_xl2 + 6400000;       // 6.4M
    float* p_wbuf = p_u2 + 6400000;        // 6.4M
    float* p_ea   = p_wbuf + 6400000;      // 512000
    float* p_ea2  = p_ea + 512000;         // 512000
    float* p_eo1  = p_ea2 + 512000;        // 1024000
    float* p_eo2  = p_eo1 + 1024000;       // 512000
    float* p_a1   = p_eo2 + 512000;        // 640000
    float* p_a2   = p_a1 + 640000;         // 320000
    float* p_an1  = p_a2 + 320000;         // 100000
    float* p_ae1  = p_an1 + 100000;        // 8000
    float* p_an2  = p_ae1 + 8000;          // 50000
    float* p_ae2  = p_an2 + 50000;         // 4000

    // int arena layout
    int* p_ncnt  = I;                      // 50000
    int* p_nfill = p_ncnt + 50000;         // 50000
    int* p_ecnt  = p_nfill + 50000;        // 4000
    int* p_efill = p_ecnt + 4000;          // 4000   (first 108000 ints zeroed)
    int* p_noff  = p_efill + 4000;         // 50001
    int* p_eoff  = p_noff + 50001;         // 4001
    int* p_nent  = p_eoff + 4001;          // 320000
    int* p_eent  = p_nent + 320000;        // 320000
    int* p_bsum  = p_eent + 320000;        // 256
    int* p_boff  = p_bsum + 256;           // 256

    const float invn = 1.f / (float)NN;
    const int EB = (EE + 255) / 256;       // 1250
    const int NWB = (NN + 7) / 8;          // 6250 (warp-per-node kernels)
    const int MWB = (MM + 7) / 8;          // 500
    const int GB2 = (NN + 127) / 128;      // 391 (gemm2 row blocks)
    const int SB = (NN + 255) / 256;       // 196

    // ---- zero counters / stats ----
    k_zero_i<<<(108000 + 255) / 256, 256>>>(I, 108000);
    k_zero_f<<<(51024 + 255) / 256, 256>>>(F, 51024);   // Dn + stats

    // ---- CSR build ----
    k_count<<<EB, 256>>>(he_n, he_e, he_w, p_ncnt, p_ecnt, p_Dn);
    k_scan_red<<<196, 256>>>(p_ncnt, p_bsum, NN);
    k_scan_top<<<1, 256>>>(p_bsum, p_boff, 196, p_noff, NN);
    k_scan_fin<<<196, 256>>>(p_ncnt, p_boff, p_noff, NN);
    k_scan_red<<<16, 256>>>(p_ecnt, p_bsum, MM);
    k_scan_top<<<1, 256>>>(p_bsum, p_boff, 16, p_eoff, MM);
    k_scan_fin<<<16, 256>>>(p_ecnt, p_boff, p_eoff, MM);
    k_fill<<<EB, 256>>>(he_n, he_e, p_noff, p_eoff, p_nfill, p_efill, p_nent, p_eent);
    k_prepatt<<<1, 128>>>(h1_w, h1_att, h2_w, h2_att, p_wx1, p_we1, p_wx2, p_we2);

    // ---- layer 1: z1 = lrelu(x @ lin1_w + b); BN1 stats fused -> aff1 ----
    k_gemm2<false, true, true, false, true><<<dim3(GB2, 1), 256>>>(
        x, nullptr, lin1_w, 128, lin1_b, nullptr, p_z1, NN, p_st);
    k_affine<<<1, 128>>>(p_st, bn1_g, bn1_b, p_aff, invn);

    // ---- hgconv1 (H=2) ----
    k_gemm2<true, false, false, false, false><<<dim3(GB2, 2), 256>>>(
        p_z1, p_aff, h1_w, 256, nullptr, nullptr, p_xl1, NN, nullptr);
    k_rowvec<2, true><<<NWB, 256>>>(p_z1, p_aff, p_wx1, p_an1, NN);
    k_ea<<<MM, 128>>>(p_z1, p_aff, p_eoff, p_eent, he_n, p_ea);
    k_rowvec<2, false><<<MWB, 256>>>(p_ea, nullptr, p_we1, p_ae1, MM);
    k_softmax<2><<<NWB, 256>>>(p_an1, p_ae1, p_noff, p_nent, he_e, p_a1, NN);
    k_eo<2><<<MM, 256>>>(p_xl1, p_a1, p_eoff, p_eent, he_n, p_eo1);
    k_out<2><<<NWB, 256>>>(p_eo1, p_a1, p_noff, p_nent, he_e, p_z1, p_aff, h1_b, p_Dn, p_u1, NN);
    k_colstats<<<SB, 128>>>(p_u1, NN, p_st + 256);
    k_affine<<<1, 128>>>(p_st + 256, bn2_g, bn2_b, p_aff + 256, invn);

    // ---- hgconv2 (H=1) ----
    k_gemm2<true, false, false, false, false><<<dim3(GB2, 1), 256>>>(
        p_u1, p_aff + 256, h2_w, 128, nullptr, nullptr, p_xl2, NN, nullptr);
    k_rowvec<1, true><<<NWB, 256>>>(p_u1, p_aff + 256, p_wx2, p_an2, NN);
    k_ea<<<MM, 128>>>(p_u1, p_aff + 256, p_eoff, p_eent, he_n, p_ea2);
    k_rowvec<1, false><<<MWB, 256>>>(p_ea2, nullptr, p_we2, p_ae2, MM);
    k_softmax<1><<<NWB, 256>>>(p_an2, p_ae2, p_noff, p_nent, he_e, p_a2, NN);
    k_eo<1><<<MM, 128>>>(p_xl2, p_a2, p_eoff, p_eent, he_n, p_eo2);
    k_out<1><<<NWB, 256>>>(p_eo2, p_a2, p_noff, p_nent, he_e, p_u1, p_aff + 256, h2_b, p_Dn, p_u2, NN);
    k_colstats<<<SB, 128>>>(p_u2, NN, p_st + 512);
    k_affine<<<1, 128>>>(p_st + 512, bn3_g, bn3_b, p_aff + 512, invn);

    // ---- final: w = x + lrelu(affine3(u2) @ lin2_w + b2); BN4 stats fused ----
    k_gemm2<true, true, true, true, true><<<dim3(GB2, 1), 256>>>(
        p_u2, p_aff + 512, lin2_w, 128, lin2_b, x, p_wbuf, NN, p_st + 768);
    k_affine<<<1, 128>>>(p_st + 768, bn4_g, bn4_b, p_aff + 768, invn);
    k_final<<<(NN * 128 + 255) / 256, 256>>>(p_wbuf, p_aff + 768, out, NN * 128);
}